// round 2
// baseline (speedup 1.0000x reference)
#include <cuda_runtime.h>
#include <cuda_bf16.h>
#include <math.h>

#define NN 50000
#define EE 500000
#define HD 128
#define NH 8
#define DD 16
#define CLAMPV 5.0f

// bf16 smem pitch for K' fragments (conflict-free for 8x4 quad pattern)
#define KP 104
#define EDGE_SMEM_BYTES (128*KP*2 /*As*/ + 128*KP*2 /*Bs*/ + 128*128*4 /*Ex*/ + 512 /*Aw*/)

// ---------------- scratch ----------------------------------------------------
__device__ float g_Qh[NN * HD];
__device__ float g_Kh[NN * HD];
__device__ float g_Vh[NN * HD];
__device__ float g_eexp[(size_t)EE * NH];
__device__ float g_denom[NN * NH];
__device__ float g_rowV[NN * HD];

// ---------------- helpers ----------------------------------------------------
__device__ __forceinline__ void red_add_v4(float* addr, float a, float b, float c, float d) {
    asm volatile("red.global.add.v4.f32 [%0], {%1,%2,%3,%4};"
                 :: "l"(addr), "f"(a), "f"(b), "f"(c), "f"(d)
                 : "memory");
}

__device__ __forceinline__ void mma_bf16(float& c0, float& c1, float& c2, float& c3,
                                         unsigned a0, unsigned a1, unsigned a2, unsigned a3,
                                         unsigned b0, unsigned b1) {
    asm volatile(
        "mma.sync.aligned.m16n8k16.row.col.f32.bf16.bf16.f32 "
        "{%0,%1,%2,%3}, {%4,%5,%6,%7}, {%8,%9}, {%0,%1,%2,%3};\n"
        : "+f"(c0), "+f"(c1), "+f"(c2), "+f"(c3)
        : "r"(a0), "r"(a1), "r"(a2), "r"(a3), "r"(b0), "r"(b1));
}

// ---------------- zero scratch ------------------------------------------------
__global__ void zero_kernel() {
    int stride = gridDim.x * blockDim.x;
    int total = NN * HD + NN * NH;
    for (int i = blockIdx.x * blockDim.x + threadIdx.x; i < total; i += stride) {
        if (i < NN * HD) g_rowV[i] = 0.f;
        else             g_denom[i - NN * HD] = 0.f;
    }
}

// ---------------- node GEMM: Qh/Kh/Vh = x @ W + b (fp32, unchanged) ----------
__global__ __launch_bounds__(256) void node_gemm(
    const float* __restrict__ x,
    const float* __restrict__ WQ, const float* __restrict__ bQ,
    const float* __restrict__ WK, const float* __restrict__ bK,
    const float* __restrict__ WV, const float* __restrict__ bV,
    float* __restrict__ d_out)
{
    const int which = blockIdx.y;
    const float* W    = (which == 0) ? WQ : (which == 1) ? WK : WV;
    const float* bias = (which == 0) ? bQ : (which == 1) ? bK : bV;
    float* out        = (which == 0) ? g_Qh : (which == 1) ? g_Kh : g_Vh;

    __shared__ float As[64 * 16];
    __shared__ float Bs[16 * 128];

    const int tid = threadIdx.x;
    const int tx = tid & 15, ty = tid >> 4;
    const int m0 = blockIdx.x * 64;

    const int ar = tid >> 2;
    const int ac = (tid & 3) * 4;
    const int brow = tid >> 4;
    const int bcol = (tid & 15) * 8;

    float acc[4][8];
    #pragma unroll
    for (int i = 0; i < 4; i++)
        #pragma unroll
        for (int j = 0; j < 8; j++) acc[i][j] = 0.f;

    for (int k0 = 0; k0 < 128; k0 += 16) {
        float4 av = make_float4(0.f, 0.f, 0.f, 0.f);
        int m = m0 + ar;
        if (m < NN) av = *(const float4*)&x[(size_t)m * 128 + k0 + ac];
        *(float4*)&As[ar * 16 + ac] = av;
        *(float4*)&Bs[brow * 128 + bcol]     = *(const float4*)&W[(size_t)(k0 + brow) * 128 + bcol];
        *(float4*)&Bs[brow * 128 + bcol + 4] = *(const float4*)&W[(size_t)(k0 + brow) * 128 + bcol + 4];
        __syncthreads();
        #pragma unroll
        for (int k = 0; k < 16; k++) {
            float a[4], b[8];
            #pragma unroll
            for (int i = 0; i < 4; i++) a[i] = As[(ty * 4 + i) * 16 + k];
            #pragma unroll
            for (int j = 0; j < 8; j++) b[j] = Bs[k * 128 + tx * 8 + j];
            #pragma unroll
            for (int i = 0; i < 4; i++)
                #pragma unroll
                for (int j = 0; j < 8; j++)
                    acc[i][j] = fmaf(a[i], b[j], acc[i][j]);
        }
        __syncthreads();
    }

    #pragma unroll
    for (int i = 0; i < 4; i++) {
        int m = m0 + ty * 4 + i;
        if (m >= NN) continue;
        #pragma unroll
        for (int j = 0; j < 8; j++) {
            int c = tx * 8 + j;
            float v = acc[i][j] + bias[c];
            out[(size_t)m * 128 + c] = v;
            if (which == 0) d_out[(size_t)m * 128 + c] = v;
        }
    }
}

// ---------------- edge GEMM (bf16 tensor core, hi/lo split) + fused epilogue -
// Tile: 128 edges x 128 cols. K=128 fp32 -> K'=384 bf16 via [ah,al,ah]·[bh,bh,bl].
// Epilogue: conn = Kh[src]+Qh[dst]+signed_sqrt(Ex1*Ex2) -> d_out
//           score = clip(conn.Aw); eexp=exp(score); atomic denom.
__global__ __launch_bounds__(256) void edge_gemm_bf16(
    const float* __restrict__ ea,
    const float* __restrict__ WE, const float* __restrict__ bE,
    const int* __restrict__ edge_index,
    const float* __restrict__ Aw,
    float* __restrict__ d_out)
{
    extern __shared__ char smem[];
    __nv_bfloat16* As = (__nv_bfloat16*)smem;                    // [128][KP]
    __nv_bfloat16* Bs = (__nv_bfloat16*)(smem + 128 * KP * 2);   // [128][KP] (n-major)
    float* Ex  = (float*)(smem + 2 * 128 * KP * 2);              // [128][128]
    float* AwS = (float*)(smem + 2 * 128 * KP * 2 + 128 * 128 * 4);

    const int tid  = threadIdx.x;
    const int lane = tid & 31;
    const int wrp  = tid >> 5;
    const int g    = lane >> 2;      // 0..7
    const int tg   = lane & 3;       // 0..3
    const int m0   = blockIdx.x * 128;
    const int n0   = blockIdx.y * 128;       // 0 or 128 (heads 0-3 / 4-7)
    const int warp_m = (wrp & 3) * 32;
    const int warp_n = (wrp >> 2) * 64;

    if (tid < 128) AwS[tid] = Aw[tid];

    float c[2][8][4];
    #pragma unroll
    for (int mt = 0; mt < 2; mt++)
        #pragma unroll
        for (int nt = 0; nt < 8; nt++)
            #pragma unroll
            for (int q = 0; q < 4; q++) c[mt][nt][q] = 0.f;

    for (int chunk = 0; chunk < 4; chunk++) {
        const int k0 = chunk * 32;

        // --- load+convert A chunk: ea[m0..m0+127][k0..k0+31] fp32 -> bf16 hi/lo
        #pragma unroll
        for (int it = 0; it < 4; it++) {
            int idx = tid + it * 256;        // 0..1023 float4s
            int row = idx >> 3;              // 0..127
            int c4  = idx & 7;               // 0..7
            float4 v = make_float4(0.f, 0.f, 0.f, 0.f);
            int m = m0 + row;
            if (m < EE) v = *(const float4*)&ea[(size_t)m * 128 + k0 + c4 * 4];
            const float vv[4] = {v.x, v.y, v.z, v.w};
            #pragma unroll
            for (int j = 0; j < 4; j++) {
                float a = vv[j];
                __nv_bfloat16 ah = __float2bfloat16(a);
                __nv_bfloat16 al = __float2bfloat16(a - __bfloat162float(ah));
                int kk = c4 * 4 + j;
                As[row * KP + 3 * kk + 0] = ah;
                As[row * KP + 3 * kk + 1] = al;
                As[row * KP + 3 * kk + 2] = ah;
            }
        }
        // --- load+convert+transpose B chunk: WE[k0..k0+31][n0..n0+127]
        #pragma unroll
        for (int it = 0; it < 4; it++) {
            int idx = tid + it * 256;
            int kk = idx >> 5;               // 0..31
            int n4 = (idx & 31) * 4;         // 0..124
            float4 w = *(const float4*)&WE[(size_t)(k0 + kk) * 256 + n0 + n4];
            const float ww[4] = {w.x, w.y, w.z, w.w};
            #pragma unroll
            for (int j = 0; j < 4; j++) {
                float b = ww[j];
                __nv_bfloat16 bh = __float2bfloat16(b);
                __nv_bfloat16 bl = __float2bfloat16(b - __bfloat162float(bh));
                int n = n4 + j;
                Bs[n * KP + 3 * kk + 0] = bh;
                Bs[n * KP + 3 * kk + 1] = bh;
                Bs[n * KP + 3 * kk + 2] = bl;
            }
        }
        __syncthreads();

        // --- mma over K' = 96 (6 steps of k16)
        #pragma unroll
        for (int ks = 0; ks < 6; ks++) {
            const int k16 = ks * 16;
            unsigned a[2][4];
            #pragma unroll
            for (int mt = 0; mt < 2; mt++) {
                int r0 = warp_m + mt * 16 + g;
                a[mt][0] = *(const unsigned*)&As[r0 * KP + k16 + 2 * tg];
                a[mt][1] = *(const unsigned*)&As[(r0 + 8) * KP + k16 + 2 * tg];
                a[mt][2] = *(const unsigned*)&As[r0 * KP + k16 + 2 * tg + 8];
                a[mt][3] = *(const unsigned*)&As[(r0 + 8) * KP + k16 + 2 * tg + 8];
            }
            unsigned b[8][2];
            #pragma unroll
            for (int nt = 0; nt < 8; nt++) {
                int nrow = warp_n + nt * 8 + g;
                b[nt][0] = *(const unsigned*)&Bs[nrow * KP + k16 + 2 * tg];
                b[nt][1] = *(const unsigned*)&Bs[nrow * KP + k16 + 2 * tg + 8];
            }
            #pragma unroll
            for (int mt = 0; mt < 2; mt++)
                #pragma unroll
                for (int nt = 0; nt < 8; nt++)
                    mma_bf16(c[mt][nt][0], c[mt][nt][1], c[mt][nt][2], c[mt][nt][3],
                             a[mt][0], a[mt][1], a[mt][2], a[mt][3],
                             b[nt][0], b[nt][1]);
        }
        __syncthreads();
    }

    // --- C fragments (+bias) -> Ex smem
    #pragma unroll
    for (int mt = 0; mt < 2; mt++) {
        int r0 = warp_m + mt * 16 + g;
        #pragma unroll
        for (int nt = 0; nt < 8; nt++) {
            int col = warp_n + nt * 8 + 2 * tg;
            float b0 = bE[n0 + col], b1 = bE[n0 + col + 1];
            Ex[r0 * 128 + col]           = c[mt][nt][0] + b0;
            Ex[r0 * 128 + col + 1]       = c[mt][nt][1] + b1;
            Ex[(r0 + 8) * 128 + col]     = c[mt][nt][2] + b0;
            Ex[(r0 + 8) * 128 + col + 1] = c[mt][nt][3] + b1;
        }
    }
    __syncthreads();

    float* connOut = d_out + (size_t)NN * 128;

    // conn: 128 edges * 4 heads * 16 dims
    for (int idx = tid; idx < 128 * 64; idx += 256) {
        int el  = idx >> 6;
        int rem = idx & 63;
        int gg  = rem >> 4;
        int d   = rem & 15;
        int e   = m0 + el;
        float x1 = Ex[el * 128 + gg * 32 + d];
        float x2 = Ex[el * 128 + gg * 32 + 16 + d];
        float s2 = x1 * x2;
        float sc2 = copysignf(sqrtf(fabsf(s2)), s2);
        if (e < EE) {
            int h = blockIdx.y * 4 + gg;
            int src = edge_index[e];
            int dst = edge_index[EE + e];
            float conn = g_Kh[(size_t)src * 128 + h * 16 + d]
                       + g_Qh[(size_t)dst * 128 + h * 16 + d] + sc2;
            connOut[(size_t)e * 128 + h * 16 + d] = conn;
            Ex[el * 128 + gg * 32 + d] = conn;
        }
    }
    __syncthreads();

    // score per (edge, head): 512 tasks
    #pragma unroll
    for (int it = 0; it < 2; it++) {
        int t  = tid + it * 256;
        int el = t >> 2;
        int gg = t & 3;
        int e  = m0 + el;
        if (e < EE) {
            int h = blockIdx.y * 4 + gg;
            float s = 0.f;
            #pragma unroll
            for (int d = 0; d < 16; d++)
                s = fmaf(Ex[el * 128 + gg * 32 + d], AwS[d * 8 + h], s);
            s = fminf(fmaxf(s, -CLAMPV), CLAMPV);
            float eev = expf(s);
            g_eexp[(size_t)e * 8 + h] = eev;
            int dst = edge_index[EE + e];
            atomicAdd(&g_denom[dst * 8 + h], eev);
        }
    }
}

// ---------------- aggregation: warp per edge ---------------------------------
__global__ __launch_bounds__(256) void aggregate(
    const int* __restrict__ edge_index,
    float* __restrict__ d_out)
{
    const int warp = threadIdx.x >> 5;
    const int lane = threadIdx.x & 31;
    const size_t e = (size_t)blockIdx.x * 8 + warp;
    if (e >= EE) return;

    const int src = edge_index[e];
    const int dst = edge_index[EE + e];
    const int h = lane >> 2;

    float den  = g_denom[dst * 8 + h];
    float attn = g_eexp[e * 8 + h] / (den + 1e-16f);

    const float4* Vh4   = (const float4*)g_Vh;
    const float4* conn4 = (const float4*)(d_out + (size_t)NN * 128);
    float4 v = Vh4[(size_t)src * 32 + lane];
    float4 c = conn4[e * 32 + lane];

    float4* out4 = (float4*)d_out;
    float4* row4 = (float4*)g_rowV;
    red_add_v4((float*)&out4[(size_t)dst * 32 + lane], v.x * attn, v.y * attn, v.z * attn, v.w * attn);
    red_add_v4((float*)&row4[(size_t)dst * 32 + lane], c.x * attn, c.y * attn, c.z * attn, c.w * attn);
}

// ---------------- finalize: Vo += rowV @ VeRow per head ----------------------
__global__ __launch_bounds__(128) void finalize(
    const float* __restrict__ VeRow,
    float* __restrict__ d_out)
{
    __shared__ float Vs[2048];
    const int tid = threadIdx.x;
    for (int i = tid; i < 2048; i += 128) Vs[i] = VeRow[i];
    __syncthreads();

    const int h = tid >> 4, c = tid & 15;
    const int n0 = blockIdx.x * 32;
    const int nend = (n0 + 32 < NN) ? n0 + 32 : NN;
    for (int n = n0; n < nend; n++) {
        float acc = 0.f;
        #pragma unroll
        for (int d = 0; d < 16; d++)
            acc = fmaf(g_rowV[(size_t)n * 128 + h * 16 + d], Vs[d * 128 + h * 16 + c], acc);
        d_out[(size_t)n * 128 + h * 16 + c] += acc;
    }
}

// ---------------- launch ------------------------------------------------------
extern "C" void kernel_launch(void* const* d_in, const int* in_sizes, int n_in,
                              void* d_out, int out_size)
{
    const float* x    = (const float*)d_in[0];
    const float* ea   = (const float*)d_in[1];
    const int*   eidx = (const int*)  d_in[2];
    const float* WQ   = (const float*)d_in[3];
    const float* bQ   = (const float*)d_in[4];
    const float* WK   = (const float*)d_in[5];
    const float* bK   = (const float*)d_in[6];
    const float* WE   = (const float*)d_in[7];
    const float* bE   = (const float*)d_in[8];
    const float* WV   = (const float*)d_in[9];
    const float* bV   = (const float*)d_in[10];
    const float* Aw   = (const float*)d_in[11];
    const float* VeRow= (const float*)d_in[12];
    float* out = (float*)d_out;

    static bool attr_set = false;
    if (!attr_set) {
        cudaFuncSetAttribute(edge_gemm_bf16,
                             cudaFuncAttributeMaxDynamicSharedMemorySize,
                             EDGE_SMEM_BYTES);
        attr_set = true;
    }

    zero_kernel<<<1024, 256>>>();

    dim3 gn((NN + 63) / 64, 3);
    node_gemm<<<gn, 256>>>(x, WQ, bQ, WK, bK, WV, bV, out);

    dim3 ge((EE + 127) / 128, 2);
    edge_gemm_bf16<<<ge, 256, EDGE_SMEM_BYTES>>>(ea, WE, bE, eidx, Aw, out);

    aggregate<<<(EE + 7) / 8, 256>>>(eidx, out);

    finalize<<<(NN + 31) / 32, 128>>>(VeRow, out);
}